// round 1
// baseline (speedup 1.0000x reference)
#include <cuda_runtime.h>

// Problem shape (fixed by reference setup_inputs)
#define BATCH 8
#define MPRED 100
#define NGT   32
#define HWPIX 65536   // 256*256

// Scratch: matched pred index per (b, n). __device__ global (no allocation).
__device__ int g_gtm[BATCH * NGT];

// ---------------------------------------------------------------------------
// Kernel 1: per-batch greedy matching. One warp per batch; lane = GT index.
// Computes gtm / biou / flags and writes the small output tails.
// ---------------------------------------------------------------------------
__global__ void match_kernel(const float* __restrict__ pred_boxes,  // [B,M,4]
                             const float* __restrict__ gt_boxes,    // [B,N,4]
                             const float* __restrict__ pred_scores, // [B,M]
                             const float* __restrict__ mask_score,  // [B,M]
                             float* __restrict__ out)
{
    const int b    = blockIdx.x;
    const int lane = threadIdx.x;   // 0..31, one per GT

    __shared__ float s_score[MPRED];
    __shared__ int   s_order[MPRED];

    const float* ps = pred_scores + b * MPRED;
    for (int i = lane; i < MPRED; i += 32) s_score[i] = ps[i];
    __syncwarp();

    // Stable descending argsort via rank sort (ties -> lower index first),
    // matching jnp.argsort(-scores).
    for (int i = lane; i < MPRED; i += 32) {
        const float si = s_score[i];
        int rank = 0;
        #pragma unroll 4
        for (int j = 0; j < MPRED; j++) {
            const float sj = s_score[j];
            rank += (sj > si) || (sj == si && j < i);
        }
        s_order[rank] = i;
    }
    __syncwarp();

    // This lane's GT box
    const float* gb = gt_boxes + (b * NGT + lane) * 4;
    const float g0 = gb[0], g1 = gb[1], g2 = gb[2], g3 = gb[3];
    const float area2 = (g2 - g0) * (g3 - g1);

    int   gtm  = -1;
    float biou = 0.0f;

    const float* pb = pred_boxes + b * MPRED * 4;

    for (int t = 0; t < MPRED; t++) {
        const int i = s_order[t];
        // Broadcast load of pred box i (all lanes same address -> L1 broadcast)
        const float p0 = pb[i * 4 + 0];
        const float p1 = pb[i * 4 + 1];
        const float p2 = pb[i * 4 + 2];
        const float p3 = pb[i * 4 + 3];
        const float area1 = (p2 - p0) * (p3 - p1);

        const float lx = fmaxf(p0, g0), ly = fmaxf(p1, g1);
        const float rx = fminf(p2, g2), ry = fminf(p3, g3);
        const float w  = fmaxf(rx - lx, 0.0f);
        const float h  = fmaxf(ry - ly, 0.0f);
        const float inter = w * h;
        const float iou = inter / (area1 + area2 - inter);

        // Faithful to reference: gt available iff gtm <= 0 (intentional "bug")
        const float cand = (gtm <= 0 && iou >= 0.5f) ? iou : -1.0f;

        // Warp argmax with tie-break to lowest lane (== jnp.argmax semantics)
        float v = cand;
        int   m = lane;
        #pragma unroll
        for (int off = 16; off; off >>= 1) {
            const float ov = __shfl_down_sync(0xffffffffu, v, off);
            const int   om = __shfl_down_sync(0xffffffffu, m, off);
            if (ov > v || (ov == v && om < m)) { v = ov; m = om; }
        }
        v = __shfl_sync(0xffffffffu, v, 0);
        m = __shfl_sync(0xffffffffu, m, 0);

        const bool update = (s_score[i] >= 0.0f) && (v >= 0.5f);
        if (update && lane == m) { gtm = i; biou = v; }
    }

    // Emit small outputs
    const int bn = b * NGT + lane;
    g_gtm[bn] = gtm;

    float* flags_out = out + (long long)BATCH * NGT * HWPIX;
    float* gtm_out   = flags_out + BATCH * NGT;
    float* biou_out  = gtm_out   + BATCH * NGT;

    flags_out[bn] = (gtm > -1) ? mask_score[b * MPRED + gtm] : 0.0f;
    gtm_out[bn]   = (float)gtm;
    biou_out[bn]  = biou;
}

// ---------------------------------------------------------------------------
// Kernel 2: mask gather / zero-fill. 67 MB of stores; HBM-bound.
// grid = (64, B*N), block = 256; each thread moves one float4.
// ---------------------------------------------------------------------------
__global__ void gather_kernel(const float* __restrict__ pred_masks, // [B,M,H,W]
                              float* __restrict__ out)              // [B,N,H,W] at offset 0
{
    const int bn = blockIdx.y;          // 0..255
    const int b  = bn >> 5;             // / NGT
    const int g  = g_gtm[bn];

    const int idx4 = blockIdx.x * blockDim.x + threadIdx.x;   // 0..16383
    float4* o = reinterpret_cast<float4*>(out) + (long long)bn * (HWPIX / 4) + idx4;

    if (g > -1) {
        const float4* src = reinterpret_cast<const float4*>(pred_masks)
                          + (long long)(b * MPRED + g) * (HWPIX / 4) + idx4;
        *o = *src;
    } else {
        *o = make_float4(0.0f, 0.0f, 0.0f, 0.0f);
    }
}

// ---------------------------------------------------------------------------
extern "C" void kernel_launch(void* const* d_in, const int* in_sizes, int n_in,
                              void* d_out, int out_size)
{
    const float* pred_boxes  = (const float*)d_in[0];
    const float* gt_boxes    = (const float*)d_in[1];
    const float* pred_scores = (const float*)d_in[2];
    const float* pred_masks  = (const float*)d_in[3];
    const float* mask_score  = (const float*)d_in[4];
    float* out = (float*)d_out;

    match_kernel<<<BATCH, 32>>>(pred_boxes, gt_boxes, pred_scores, mask_score, out);

    dim3 grid(HWPIX / 4 / 256, BATCH * NGT);   // (64, 256)
    gather_kernel<<<grid, 256>>>(pred_masks, out);
}

// round 2
// speedup vs baseline: 1.6141x; 1.6141x over previous
#include <cuda_runtime.h>

// Problem shape (fixed by reference setup_inputs)
#define BATCH 8
#define MPRED 100
#define NGT   32
#define HWPIX 65536   // 256*256

// Scratch: matched pred index per (b, n). __device__ global (no allocation).
__device__ int g_gtm[BATCH * NGT];

// ---------------------------------------------------------------------------
// Kernel 1: per-batch greedy matching. One warp per batch; lane = GT index.
// Strategy: precompute IoU matrix in shared (parallel), prune preds with no
// IoU>=thr candidate, rank-sort only the survivors, then run the short serial
// greedy scan entirely out of shared/registers with HW REDUX argmax.
// ---------------------------------------------------------------------------
__global__ void match_kernel(const float* __restrict__ pred_boxes,  // [B,M,4]
                             const float* __restrict__ gt_boxes,    // [B,N,4]
                             const float* __restrict__ pred_scores, // [B,M]
                             const float* __restrict__ mask_score,  // [B,M]
                             float* __restrict__ out)
{
    const int b    = blockIdx.x;
    const int lane = threadIdx.x;   // 0..31, one per GT

    __shared__ float4 s_pbox[MPRED];       // pred boxes
    __shared__ float  s_score[MPRED];      // pred scores
    __shared__ float  s_iou[MPRED * NGT];  // iou[p][gt]
    __shared__ int    s_hits[MPRED];       // pred indices with >=1 candidate
    __shared__ int    s_sorted[MPRED];     // hits sorted by (score desc, idx asc)
    __shared__ int    s_nhits;

    // Stage pred boxes + scores in shared
    const float4* pb4 = reinterpret_cast<const float4*>(pred_boxes + b * MPRED * 4);
    const float*  ps  = pred_scores + b * MPRED;
    for (int i = lane; i < MPRED; i += 32) {
        s_pbox[i]  = pb4[i];
        s_score[i] = ps[i];
    }
    __syncwarp();

    // This lane's GT box
    const float* gb = gt_boxes + (b * NGT + lane) * 4;
    const float g0 = gb[0], g1 = gb[1], g2 = gb[2], g3 = gb[3];
    const float area2 = (g2 - g0) * (g3 - g1);

    // Phase A: full IoU matrix + hit pruning (parallel, no serial deps)
    int nhits = 0;
    for (int p = 0; p < MPRED; p++) {
        const float4 pbx = s_pbox[p];           // broadcast LDS
        const float area1 = (pbx.z - pbx.x) * (pbx.w - pbx.y);
        const float lx = fmaxf(pbx.x, g0), ly = fmaxf(pbx.y, g1);
        const float rx = fminf(pbx.z, g2), ry = fminf(pbx.w, g3);
        const float w  = fmaxf(rx - lx, 0.0f);
        const float h  = fmaxf(ry - ly, 0.0f);
        const float inter = w * h;
        const float iou = inter / (area1 + area2 - inter);
        s_iou[p * NGT + lane] = iou;
        const unsigned bal = __ballot_sync(0xffffffffu, iou >= 0.5f);
        // score >= SCORE_THR(0) is part of the update gate; filter here
        if (lane == 0 && bal != 0u && s_score[p] >= 0.0f) s_hits[nhits++] = p;
    }
    if (lane == 0) s_nhits = nhits;
    __syncwarp();
    const int K = s_nhits;

    // Phase B: stable descending rank-sort of the K hit preds
    // (matches jnp.argsort(-scores) restricted to the hit set)
    for (int t = lane; t < K; t += 32) {
        const int   hi = s_hits[t];
        const float si = s_score[hi];
        int rank = 0;
        for (int u = 0; u < K; u++) {
            const int   hu = s_hits[u];
            const float su = s_score[hu];
            rank += (su > si) || (su == si && hu < hi);
        }
        s_sorted[rank] = hi;
    }
    __syncwarp();

    // Phase C: serial greedy scan over the K candidates only
    int   gtm  = -1;
    float biou = 0.0f;

    for (int t = 0; t < K; t++) {
        const int   i   = s_sorted[t];
        const float iou = s_iou[i * NGT + lane];
        // Faithful to reference: gt available iff gtm <= 0 (intentional "bug")
        const bool  valid = (gtm <= 0) && (iou >= 0.5f);
        // positive-float bits are monotone as u32; invalid -> 0
        const unsigned key  = valid ? __float_as_uint(iou) : 0u;
        const unsigned kmax = __reduce_max_sync(0xffffffffu, key);
        if (kmax != 0u) {   // some valid candidate with iou >= 0.5
            const unsigned bal = __ballot_sync(0xffffffffu, key == kmax);
            const int m = __ffs(bal) - 1;   // lowest lane = jnp.argmax tie-break
            if (lane == m) { gtm = i; biou = iou; }
        }
    }

    // Emit small outputs
    const int bn = b * NGT + lane;
    g_gtm[bn] = gtm;

    float* flags_out = out + (long long)BATCH * NGT * HWPIX;
    float* gtm_out   = flags_out + BATCH * NGT;
    float* biou_out  = gtm_out   + BATCH * NGT;

    flags_out[bn] = (gtm > -1) ? mask_score[b * MPRED + gtm] : 0.0f;
    gtm_out[bn]   = (float)gtm;
    biou_out[bn]  = biou;
}

// ---------------------------------------------------------------------------
// Kernel 2: mask gather / zero-fill. 67 MB of stores; STG-issue/L2-bound.
// grid = (64, B*N), block = 256; each thread moves one float4.  (unchanged)
// ---------------------------------------------------------------------------
__global__ void gather_kernel(const float* __restrict__ pred_masks, // [B,M,H,W]
                              float* __restrict__ out)              // [B,N,H,W] at offset 0
{
    const int bn = blockIdx.y;          // 0..255
    const int b  = bn >> 5;             // / NGT
    const int g  = g_gtm[bn];

    const int idx4 = blockIdx.x * blockDim.x + threadIdx.x;   // 0..16383
    float4* o = reinterpret_cast<float4*>(out) + (long long)bn * (HWPIX / 4) + idx4;

    if (g > -1) {
        const float4* src = reinterpret_cast<const float4*>(pred_masks)
                          + (long long)(b * MPRED + g) * (HWPIX / 4) + idx4;
        *o = *src;
    } else {
        *o = make_float4(0.0f, 0.0f, 0.0f, 0.0f);
    }
}

// ---------------------------------------------------------------------------
extern "C" void kernel_launch(void* const* d_in, const int* in_sizes, int n_in,
                              void* d_out, int out_size)
{
    const float* pred_boxes  = (const float*)d_in[0];
    const float* gt_boxes    = (const float*)d_in[1];
    const float* pred_scores = (const float*)d_in[2];
    const float* pred_masks  = (const float*)d_in[3];
    const float* mask_score  = (const float*)d_in[4];
    float* out = (float*)d_out;

    match_kernel<<<BATCH, 32>>>(pred_boxes, gt_boxes, pred_scores, mask_score, out);

    dim3 grid(HWPIX / 4 / 256, BATCH * NGT);   // (64, 256)
    gather_kernel<<<grid, 256>>>(pred_masks, out);
}

// round 3
// speedup vs baseline: 2.8105x; 1.7412x over previous
#include <cuda_runtime.h>

// Problem shape (fixed by reference setup_inputs)
#define BATCH 8
#define MPRED 100
#define NGT   32
#define HWPIX 65536   // 256*256
#define F4_PER_BN (HWPIX / 4)      // 16384 float4 per (b,n) mask
#define GATHER_XBLK 4              // blocks along the pixel dim
#define F4_PER_BLK (F4_PER_BN / GATHER_XBLK)   // 4096
#define F4_PER_THR (F4_PER_BLK / 256)          // 16

// Scratch: matched pred index per (b, n). __device__ global (no allocation).
__device__ int g_gtm[BATCH * NGT];

// ---------------------------------------------------------------------------
// Kernel 1: per-batch greedy matching. One 256-thread block per batch.
// Phase A (IoU matrix + hit flags) parallel over 8 warps; Phase B/C (sort +
// serial greedy scan) in warp 0 only, entirely out of shared/registers.
// ---------------------------------------------------------------------------
__global__ void match_kernel(const float* __restrict__ pred_boxes,  // [B,M,4]
                             const float* __restrict__ gt_boxes,    // [B,N,4]
                             const float* __restrict__ pred_scores, // [B,M]
                             const float* __restrict__ mask_score,  // [B,M]
                             float* __restrict__ out)
{
    const int b    = blockIdx.x;
    const int tid  = threadIdx.x;
    const int wid  = tid >> 5;
    const int lane = tid & 31;      // lane = GT index

    __shared__ float  s_score[MPRED];
    __shared__ float  s_iou[MPRED * NGT];
    __shared__ int    s_hit[128];          // flag per pred (padded)
    __shared__ int    s_hits[MPRED];       // compacted hit pred indices
    __shared__ int    s_sorted[MPRED];
    __shared__ int    s_nhits;

    // Stage scores; init hit flags
    const float* ps = pred_scores + b * MPRED;
    for (int i = tid; i < MPRED; i += 256) s_score[i] = ps[i];
    for (int i = tid; i < 128;   i += 256) s_hit[i] = 0;
    __syncthreads();

    // This lane's GT box
    const float* gb = gt_boxes + (b * NGT + lane) * 4;
    const float g0 = gb[0], g1 = gb[1], g2 = gb[2], g3 = gb[3];
    const float area2 = (g2 - g0) * (g3 - g1);

    const float4* pb4 = reinterpret_cast<const float4*>(pred_boxes + b * MPRED * 4);

    // Phase A: each warp handles preds p = wid, wid+8, ...
    for (int p = wid; p < MPRED; p += 8) {
        const float4 pbx = pb4[p];          // broadcast within warp (L1/L2)
        const float area1 = (pbx.z - pbx.x) * (pbx.w - pbx.y);
        const float lx = fmaxf(pbx.x, g0), ly = fmaxf(pbx.y, g1);
        const float rx = fminf(pbx.z, g2), ry = fminf(pbx.w, g3);
        const float w  = fmaxf(rx - lx, 0.0f);
        const float h  = fmaxf(ry - ly, 0.0f);
        const float inter = w * h;
        const float iou = inter / (area1 + area2 - inter);
        s_iou[p * NGT + lane] = iou;
        const unsigned bal = __ballot_sync(0xffffffffu, iou >= 0.5f);
        if (lane == 0) s_hit[p] = (bal != 0u) && (s_score[p] >= 0.0f);
    }
    __syncthreads();

    if (wid == 0) {
        // Compact hit preds via 4 ballots + prefix popcounts (order: idx asc,
        // but Phase B's rank sort is storage-order agnostic anyway).
        int nh = 0;
        #pragma unroll
        for (int k = 0; k < 4; k++) {
            const int p = k * 32 + lane;
            const int f = (p < MPRED) ? s_hit[p] : 0;
            const unsigned bal = __ballot_sync(0xffffffffu, f != 0);
            if (f) {
                const int rank = nh + __popc(bal & ((1u << lane) - 1u));
                s_hits[rank] = p;
            }
            nh += __popc(bal);
        }
        if (lane == 0) s_nhits = nh;
        __syncwarp();
        const int K = s_nhits;

        // Phase B: stable descending rank-sort of the K hit preds
        for (int t = lane; t < K; t += 32) {
            const int   hi = s_hits[t];
            const float si = s_score[hi];
            int rank = 0;
            for (int u = 0; u < K; u++) {
                const int   hu = s_hits[u];
                const float su = s_score[hu];
                rank += (su > si) || (su == si && hu < hi);
            }
            s_sorted[rank] = hi;
        }
        __syncwarp();

        // Phase C: serial greedy scan over the K candidates
        int   gtm  = -1;
        float biou = 0.0f;
        for (int t = 0; t < K; t++) {
            const int   i   = s_sorted[t];
            const float iou = s_iou[i * NGT + lane];
            // Faithful to reference: gt available iff gtm <= 0 (intentional "bug")
            const bool  valid = (gtm <= 0) && (iou >= 0.5f);
            const unsigned key  = valid ? __float_as_uint(iou) : 0u;
            const unsigned kmax = __reduce_max_sync(0xffffffffu, key);
            if (kmax != 0u) {
                const unsigned bal = __ballot_sync(0xffffffffu, key == kmax);
                const int m = __ffs(bal) - 1;   // lowest lane = jnp.argmax tie-break
                if (lane == m) { gtm = i; biou = iou; }
            }
        }

        // Emit small outputs
        const int bn = b * NGT + lane;
        g_gtm[bn] = gtm;

        float* flags_out = out + (long long)BATCH * NGT * HWPIX;
        float* gtm_out   = flags_out + BATCH * NGT;
        float* biou_out  = gtm_out   + BATCH * NGT;

        flags_out[bn] = (gtm > -1) ? mask_score[b * MPRED + gtm] : 0.0f;
        gtm_out[bn]   = (float)gtm;
        biou_out[bn]  = biou;
    }
}

// ---------------------------------------------------------------------------
// Kernel 2: mask gather / zero-fill. Single-wave fat blocks:
// grid (4, B*N) = 1024 CTAs, 256 thr, 16 float4 per thread (front-batched).
// ---------------------------------------------------------------------------
__global__ void __launch_bounds__(256) gather_kernel(
                              const float* __restrict__ pred_masks, // [B,M,H,W]
                              float* __restrict__ out)              // [B,N,H,W]
{
    const int bn = blockIdx.y;          // 0..255
    const int b  = bn >> 5;             // / NGT
    const int g  = g_gtm[bn];

    const int base = blockIdx.x * F4_PER_BLK + threadIdx.x;  // float4 units
    float4* o = reinterpret_cast<float4*>(out) + (long long)bn * F4_PER_BN + base;

    if (g > -1) {
        const float4* src = reinterpret_cast<const float4*>(pred_masks)
                          + (long long)(b * MPRED + g) * F4_PER_BN + base;
        float4 v[F4_PER_THR];
        #pragma unroll
        for (int k = 0; k < F4_PER_THR; k++) v[k] = src[k * 256];
        #pragma unroll
        for (int k = 0; k < F4_PER_THR; k++) o[k * 256] = v[k];
    } else {
        const float4 z = make_float4(0.0f, 0.0f, 0.0f, 0.0f);
        #pragma unroll
        for (int k = 0; k < F4_PER_THR; k++) o[k * 256] = z;
    }
}

// ---------------------------------------------------------------------------
extern "C" void kernel_launch(void* const* d_in, const int* in_sizes, int n_in,
                              void* d_out, int out_size)
{
    const float* pred_boxes  = (const float*)d_in[0];
    const float* gt_boxes    = (const float*)d_in[1];
    const float* pred_scores = (const float*)d_in[2];
    const float* pred_masks  = (const float*)d_in[3];
    const float* mask_score  = (const float*)d_in[4];
    float* out = (float*)d_out;

    match_kernel<<<BATCH, 256>>>(pred_boxes, gt_boxes, pred_scores, mask_score, out);

    dim3 grid(GATHER_XBLK, BATCH * NGT);   // (4, 256) = 1024 CTAs, single wave
    gather_kernel<<<grid, 256>>>(pred_masks, out);
}